// round 1
// baseline (speedup 1.0000x reference)
#include <cuda_runtime.h>

#define NMAX 100000
#define FIN  512
#define HID  16

// ---------------- scratch (static device globals; no allocs) ----------------
__device__ float d_deg [NMAX];          // degree (incl self-loop)
__device__ float d_dinv[NMAX];          // deg^-1/2
__device__ float d_h1p [NMAX * HID];    // h1 * dinv[src]  (pre-scaled messages)
__device__ float d_acc1[NMAX * HID];    // layer-1 accumulator (init = self msg)
__device__ float d_gp  [NMAX];          // g * dinv[src] for layer 2
__device__ float d_acc2[NMAX];          // layer-2 accumulator

// ---------------- kernels ----------------
__global__ void k_init(int N) {
    int i = blockIdx.x * blockDim.x + threadIdx.x;
    if (i < N) d_deg[i] = 1.0f;         // self-loop
}

__global__ void k_deg(const int* __restrict__ dst, int E) {
    int e = blockIdx.x * blockDim.x + threadIdx.x;
    if (e < E) atomicAdd(&d_deg[dst[e]], 1.0f);
}

// GEMM1: h1 = x @ W1 ; then dinv, h1' = h1*dinv, acc1 init = h1' (self-loop).
// 256 threads = 256 rows per block. W1 (32KB) + padded x tile (33.8KB) in smem.
// Inner product via packed fma.rn.f32x2: 8 packed accumulators = 16 outputs.
__global__ void __launch_bounds__(256) k_gemm(const float* __restrict__ x,
                                              const float* __restrict__ W1,
                                              int N) {
    extern __shared__ float sm[];
    float* Ws = sm;                  // FIN*HID = 8192 floats
    float* xs = sm + FIN * HID;      // 256 * 33 floats (pad -> conflict-free)
    int tid = threadIdx.x;

    // load W1 into smem (coalesced float4)
    {
        const float4* W4 = (const float4*)W1;
        float4*       Wd = (float4*)Ws;
        #pragma unroll
        for (int i = 0; i < (FIN * HID / 4) / 256; i++)
            Wd[tid + i * 256] = W4[tid + i * 256];
    }

    int row = blockIdx.x * 256 + tid;
    unsigned long long acc[HID / 2];
    #pragma unroll
    for (int j = 0; j < HID / 2; j++) acc[j] = 0ull;

    for (int kt = 0; kt < FIN / 32; kt++) {
        __syncthreads();
        // stage x tile [256 rows x 32 k] (coalesced: 8 lanes cover 128B of a row)
        #pragma unroll
        for (int i = 0; i < 8; i++) {
            int fid = tid + i * 256;          // 0..2047
            int r   = fid >> 3, c4 = fid & 7; // row-in-tile, float4-col
            int gr  = blockIdx.x * 256 + r;
            float4 v = make_float4(0.f, 0.f, 0.f, 0.f);
            if (gr < N)
                v = ((const float4*)x)[(size_t)gr * (FIN / 4) + kt * 8 + c4];
            float* dp = &xs[r * 33 + c4 * 4];
            dp[0] = v.x; dp[1] = v.y; dp[2] = v.z; dp[3] = v.w;
        }
        __syncthreads();

        const ulonglong2* Wp = (const ulonglong2*)(Ws + (size_t)kt * 32 * HID);
        #pragma unroll
        for (int c = 0; c < 32; c++) {
            float xv = xs[tid * 33 + c];                    // conflict-free LDS
            unsigned long long x2;
            asm("mov.b64 %0,{%1,%1};" : "=l"(x2) : "f"(xv)); // splat
            #pragma unroll
            for (int j = 0; j < 4; j++) {
                ulonglong2 w = Wp[c * 4 + j];               // LDS.128 broadcast
                asm("fma.rn.f32x2 %0,%1,%2,%0;" : "+l"(acc[2*j])   : "l"(x2), "l"(w.x));
                asm("fma.rn.f32x2 %0,%1,%2,%0;" : "+l"(acc[2*j+1]) : "l"(x2), "l"(w.y));
            }
        }
    }

    if (row < N) {
        float dv = rsqrtf(d_deg[row]);
        d_dinv[row] = dv;
        float h[HID];
        #pragma unroll
        for (int j = 0; j < HID / 2; j++) {
            float lo, hi;
            asm("mov.b64 {%0,%1},%2;" : "=f"(lo), "=f"(hi) : "l"(acc[j]));
            h[2*j]   = lo * dv;       // pre-scale by dinv[src]
            h[2*j+1] = hi * dv;
        }
        float4* hp = (float4*)(d_h1p  + (size_t)row * HID);
        float4* ap = (float4*)(d_acc1 + (size_t)row * HID);
        #pragma unroll
        for (int q = 0; q < 4; q++) {
            float4 v = make_float4(h[4*q], h[4*q+1], h[4*q+2], h[4*q+3]);
            hp[q] = v;   // message row
            ap[q] = v;   // accumulator init = self-loop term (dinv^2 factored)
        }
    }
}

// Layer-1 edge pass: acc1[dst] += h1p[src]. 4 lanes per edge, one float4 each.
// Vector red (sm_90+) keeps it to ~1 line-visit per edge per access.
__global__ void k_edge1(const int* __restrict__ ei, int E) {
    int t = blockIdx.x * blockDim.x + threadIdx.x;
    int e = t >> 2, p = t & 3;
    if (e >= E) return;
    int s = ei[e];
    int d = ei[E + e];
    float4 v = ((const float4*)d_h1p)[(size_t)s * 4 + p];
    float* op = d_acc1 + (size_t)d * HID + p * 4;
    asm volatile("red.global.add.v4.f32 [%0],{%1,%2,%3,%4};"
                 :: "l"(op), "f"(v.x), "f"(v.y), "f"(v.z), "f"(v.w) : "memory");
}

// Per-node: h = relu(dinv*acc1 + b1); g = h.W2; store gp = g*dinv; acc2 init.
__global__ void k_layer2(const float* __restrict__ b1,
                         const float* __restrict__ W2, int N) {
    int i = blockIdx.x * blockDim.x + threadIdx.x;
    if (i >= N) return;
    float dv = d_dinv[i];
    const float4* ap = (const float4*)(d_acc1 + (size_t)i * HID);
    float g = 0.f;
    #pragma unroll
    for (int q = 0; q < 4; q++) {
        float4 a  = ap[q];
        float4 bb = ((const float4*)b1)[q];
        float4 w  = ((const float4*)W2)[q];
        g += fmaxf(fmaf(dv, a.x, bb.x), 0.f) * w.x;
        g += fmaxf(fmaf(dv, a.y, bb.y), 0.f) * w.y;
        g += fmaxf(fmaf(dv, a.z, bb.z), 0.f) * w.z;
        g += fmaxf(fmaf(dv, a.w, bb.w), 0.f) * w.w;
    }
    float gp = g * dv;
    d_gp[i]   = gp;
    d_acc2[i] = gp;   // self-loop term
}

// Layer-2 edge pass: acc2[dst] += gp[src] (scalar).
__global__ void k_edge2(const int* __restrict__ ei, int E) {
    int e = blockIdx.x * blockDim.x + threadIdx.x;
    if (e >= E) return;
    int s = ei[e];
    int d = ei[E + e];
    atomicAdd(&d_acc2[d], d_gp[s]);
}

__global__ void k_sig(const float* __restrict__ b2, float* __restrict__ out, int N) {
    int i = blockIdx.x * blockDim.x + threadIdx.x;
    if (i >= N) return;
    float z = fmaf(d_dinv[i], d_acc2[i], b2[0]);
    out[i] = 1.f / (1.f + __expf(-z));
}

// ---------------- launch ----------------
extern "C" void kernel_launch(void* const* d_in, const int* in_sizes, int n_in,
                              void* d_out, int out_size) {
    const float* x  = (const float*)d_in[0];
    const float* W1 = (const float*)d_in[1];
    const float* b1 = (const float*)d_in[2];
    const float* W2 = (const float*)d_in[3];
    const float* b2 = (const float*)d_in[4];
    const int*   ei = (const int*)d_in[5];

    int N = in_sizes[0] / FIN;     // 100000
    int E = in_sizes[5] / 2;       // 3200000

    const int SMEM_BYTES = (FIN * HID + 256 * 33) * (int)sizeof(float); // 66560
    cudaFuncSetAttribute(k_gemm, cudaFuncAttributeMaxDynamicSharedMemorySize,
                         SMEM_BYTES);

    k_init  <<<(N + 255) / 256, 256>>>(N);
    k_deg   <<<(E + 255) / 256, 256>>>(ei + E, E);
    k_gemm  <<<(N + 255) / 256, 256, SMEM_BYTES>>>(x, W1, N);
    {
        long long t = 4LL * E;
        k_edge1<<<(unsigned)((t + 255) / 256), 256>>>(ei, E);
    }
    k_layer2<<<(N + 255) / 256, 256>>>(b1, W2, N);
    k_edge2 <<<(E + 255) / 256, 256>>>(ei, E);
    k_sig   <<<(N + 255) / 256, 256>>>(b2, (float*)d_out, N);
}